// round 17
// baseline (speedup 1.0000x reference)
#include <cuda_runtime.h>
#include <cstdint>

#define TPB 128
#define RG_BYTES (TPB * 19 * 4)
#define COV_BYTES (TPB * 9 * 4)
#define HAR_BYTES (TPB * 12 * 4)

struct CamParams {
    float c2w[9];
    float t[3];
    float Kinv[9];
    float mult;
};

__device__ __forceinline__ void compute_cam(
    const float* __restrict__ ext, const float* __restrict__ intr,
    const unsigned int* __restrict__ hptr, const unsigned int* __restrict__ wptr,
    int b, CamParams* cam)
{
    const float* E = ext + b * 16;
    const float* K = intr + b * 9;
#pragma unroll
    for (int i = 0; i < 3; i++) {
        cam->c2w[i * 3 + 0] = E[i * 4 + 0];
        cam->c2w[i * 3 + 1] = E[i * 4 + 1];
        cam->c2w[i * 3 + 2] = E[i * 4 + 2];
        cam->t[i]           = E[i * 4 + 3];
    }
    float k00 = K[0], k01 = K[1], k02 = K[2];
    float k10 = K[3], k11 = K[4], k12 = K[5];
    float k20 = K[6], k21 = K[7], k22 = K[8];
    float det = k00 * (k11 * k22 - k12 * k21)
              - k01 * (k10 * k22 - k12 * k20)
              + k02 * (k10 * k21 - k11 * k20);
    float id = 1.0f / det;
    cam->Kinv[0] = (k11 * k22 - k12 * k21) * id;
    cam->Kinv[1] = (k02 * k21 - k01 * k22) * id;
    cam->Kinv[2] = (k01 * k12 - k02 * k11) * id;
    cam->Kinv[3] = (k12 * k20 - k10 * k22) * id;
    cam->Kinv[4] = (k00 * k22 - k02 * k20) * id;
    cam->Kinv[5] = (k02 * k10 - k00 * k12) * id;
    cam->Kinv[6] = (k10 * k21 - k11 * k20) * id;
    cam->Kinv[7] = (k01 * k20 - k00 * k21) * id;
    cam->Kinv[8] = (k00 * k11 - k01 * k10) * id;

    unsigned hv = hptr[0], wv = wptr[0];
    float hf = (hv < 100000u) ? (float)hv : __uint_as_float(hv);
    float wf = (wv < 100000u) ? (float)wv : __uint_as_float(wv);
    float px = 1.0f / wf, py = 1.0f / hf;
    float det2 = k00 * k11 - k01 * k10;
    cam->mult = 0.1f * ((k11 * px - k01 * py) + (-k10 * px + k00 * py)) / det2;
}

// ---- core per-element math (cam in smem, inputs in registers) ----
struct ElemOut {
    float m0, m1, m2;
    float sc0, sc1, sc2;
    float qw, qx, qy, qz;
    float har[12];
    float cov[9];
};

__device__ __forceinline__ void compute_elem(
    const CamParams& cam, float2 uv, float depth,
    float g0, float g1, float g2,
    float qw, float qx, float qy, float qz,
    const float* sh,   // 12 floats (read lazily by caller into this buffer)
    ElemOut& o)
{
    // means
    float d0 = cam.Kinv[0] * uv.x + cam.Kinv[1] * uv.y + cam.Kinv[2];
    float d1 = cam.Kinv[3] * uv.x + cam.Kinv[4] * uv.y + cam.Kinv[5];
    float d2 = cam.Kinv[6] * uv.x + cam.Kinv[7] * uv.y + cam.Kinv[8];
    float rn = rsqrtf(d0 * d0 + d1 * d1 + d2 * d2);
    d0 *= rn; d1 *= rn; d2 *= rn;
    o.m0 = cam.t[0] + (cam.c2w[0] * d0 + cam.c2w[1] * d1 + cam.c2w[2] * d2) * depth;
    o.m1 = cam.t[1] + (cam.c2w[3] * d0 + cam.c2w[4] * d1 + cam.c2w[5] * d2) * depth;
    o.m2 = cam.t[2] + (cam.c2w[6] * d0 + cam.c2w[7] * d1 + cam.c2w[8] * d2) * depth;

    // scales
    float dm = depth * cam.mult;
    o.sc0 = (0.5f + 14.5f / (1.0f + __expf(-g0))) * dm;
    o.sc1 = (0.5f + 14.5f / (1.0f + __expf(-g1))) * dm;
    o.sc2 = (0.5f + 14.5f / (1.0f + __expf(-g2))) * dm;

    // quat normalize
    float qn = sqrtf(qw * qw + qx * qx + qy * qy + qz * qz) + 1e-8f;
    float qi = 1.0f / qn;
    o.qw = qw * qi; o.qx = qx * qi; o.qy = qy * qi; o.qz = qz * qi;

    // harmonics
    const int pr[3] = {1, 2, 0};
#pragma unroll
    for (int c = 0; c < 3; c++) {
        o.har[c * 4 + 0] = sh[c * 4 + 0];
        float s1 = sh[c * 4 + 1] * 0.025f;
        float s2 = sh[c * 4 + 2] * 0.025f;
        float s3 = sh[c * 4 + 3] * 0.025f;
#pragma unroll
        for (int i = 0; i < 3; i++) {
            int ri = pr[i];
            o.har[c * 4 + 1 + i] = cam.c2w[ri * 3 + 1] * s1
                                 + cam.c2w[ri * 3 + 2] * s2
                                 + cam.c2w[ri * 3 + 0] * s3;
        }
    }

    // cov
    float R[9];
    R[0] = 1.f - 2.f * (o.qy * o.qy + o.qz * o.qz);
    R[1] = 2.f * (o.qx * o.qy - o.qw * o.qz);
    R[2] = 2.f * (o.qx * o.qz + o.qw * o.qy);
    R[3] = 2.f * (o.qx * o.qy + o.qw * o.qz);
    R[4] = 1.f - 2.f * (o.qx * o.qx + o.qz * o.qz);
    R[5] = 2.f * (o.qy * o.qz - o.qw * o.qx);
    R[6] = 2.f * (o.qx * o.qz - o.qw * o.qy);
    R[7] = 2.f * (o.qy * o.qz + o.qw * o.qx);
    R[8] = 1.f - 2.f * (o.qx * o.qx + o.qy * o.qy);

    float T[9];
#pragma unroll
    for (int i = 0; i < 3; i++) {
        T[i * 3 + 0] = (cam.c2w[i * 3 + 0] * R[0] + cam.c2w[i * 3 + 1] * R[3]
                      + cam.c2w[i * 3 + 2] * R[6]) * o.sc0;
        T[i * 3 + 1] = (cam.c2w[i * 3 + 0] * R[1] + cam.c2w[i * 3 + 1] * R[4]
                      + cam.c2w[i * 3 + 2] * R[7]) * o.sc1;
        T[i * 3 + 2] = (cam.c2w[i * 3 + 0] * R[2] + cam.c2w[i * 3 + 1] * R[5]
                      + cam.c2w[i * 3 + 2] * R[8]) * o.sc2;
    }
#pragma unroll
    for (int i = 0; i < 3; i++)
#pragma unroll
        for (int j = 0; j <= i; j++) {
            float v = T[i * 3 + 0] * T[j * 3 + 0]
                    + T[i * 3 + 1] * T[j * 3 + 1]
                    + T[i * 3 + 2] * T[j * 3 + 2];
            o.cov[i * 3 + j] = v;
            o.cov[j * 3 + i] = v;
        }
}

// ============ main kernel: FULL tiles only, zero bounds checks ============
__global__ void __launch_bounds__(TPB, 12)
mono_gaussian_adapter_main(
    const float* __restrict__ ext, const float* __restrict__ intr,
    const float* __restrict__ coords, const float* __restrict__ depths,
    const float* __restrict__ opac, const float* __restrict__ rg,
    const unsigned int* __restrict__ hptr, const unsigned int* __restrict__ wptr,
    float* __restrict__ out, int N)
{
    __shared__ __align__(16) float buf[TPB * 21];
    __shared__ CamParams cam;
    __shared__ __align__(8) unsigned long long mbar;

    const int b   = blockIdx.y;
    const int tid = threadIdx.x;
    const int idx0 = b * N + blockIdx.x * TPB;
    const int idx  = idx0 + tid;
    const int BN   = (int)gridDim.y * N;

    const uint32_t smem_buf  = (uint32_t)__cvta_generic_to_shared(buf);
    const uint32_t smem_mbar = (uint32_t)__cvta_generic_to_shared(&mbar);

    if (tid == 0) {
        asm volatile("mbarrier.init.shared.b64 [%0], 1;" :: "r"(smem_mbar) : "memory");
        asm volatile("fence.proxy.async.shared::cta;" ::: "memory");
        asm volatile("mbarrier.arrive.expect_tx.shared.b64 _, [%0], %1;"
                     :: "r"(smem_mbar), "r"((uint32_t)RG_BYTES) : "memory");
        asm volatile("cp.async.bulk.shared::cta.global.mbarrier::complete_tx::bytes "
                     "[%0], [%1], %2, [%3];"
                     :: "r"(smem_buf), "l"(rg + (size_t)idx0 * 19),
                        "r"((uint32_t)RG_BYTES), "r"(smem_mbar) : "memory");
        compute_cam(ext, intr, hptr, wptr, b, &cam);
    }

    // streaming scalar inputs (use-once; .cs evict-first) — overlap DMA
    float2 uv   = __ldcs((const float2*)coords + idx);
    float depth = __ldcs(depths + idx);
    float op    = __ldcs(opac + idx);

    __syncthreads();   // cam ready; mbar init visible

    float* means_o = out;
    float* cov_o   = out + BN * 3;
    float* har_o   = out + BN * 12;
    float* op_o    = out + BN * 24;
    float* sc_o    = out + BN * 25;
    float* rot_o   = out + BN * 28;

    __stcs(op_o + idx, op);

    // wait for rg tile
    asm volatile(
        "{\n\t.reg .pred p;\n\t"
        "WAIT_%=:\n\t"
        "mbarrier.try_wait.parity.acquire.cta.shared::cta.b64 p, [%0], %1, 0x989680;\n\t"
        "@p bra DONE_%=;\n\t"
        "bra WAIT_%=;\n\t"
        "DONE_%=:\n\t}"
        :: "r"(smem_mbar), "r"(0u) : "memory");

    const float* grow = buf + tid * 19;   // stride 19 (odd): conflict-free
    ElemOut o;
    compute_elem(cam, uv, depth,
                 grow[0], grow[1], grow[2],
                 grow[3], grow[4], grow[5], grow[6],
                 grow + 7, o);

    // direct streaming stores: means, rot, scales
    __stcs(means_o + (size_t)idx * 3 + 0, o.m0);
    __stcs(means_o + (size_t)idx * 3 + 1, o.m1);
    __stcs(means_o + (size_t)idx * 3 + 2, o.m2);
    __stcs((float4*)rot_o + idx, make_float4(o.qw, o.qx, o.qy, o.qz));
    __stcs(sc_o + (size_t)idx * 3 + 0, o.sc0);
    __stcs(sc_o + (size_t)idx * 3 + 1, o.sc1);
    __stcs(sc_o + (size_t)idx * 3 + 2, o.sc2);

    __syncthreads();   // all smem input reads complete; safe to overwrite buf

    // stage cov (scalar stride 9, odd -> conflict-free)
#pragma unroll
    for (int i = 0; i < 9; i++) buf[tid * 9 + i] = o.cov[i];
    // stage har (STS.128, float4-stride 3 -> conflict-free)
    {
        float4* h4 = (float4*)(buf + 9 * TPB);
#pragma unroll
        for (int c = 0; c < 3; c++)
            h4[tid * 3 + c] = make_float4(o.har[c * 4 + 0], o.har[c * 4 + 1],
                                          o.har[c * 4 + 2], o.har[c * 4 + 3]);
    }
    __syncthreads();

    if (tid == 0) {
        asm volatile("fence.proxy.async.shared::cta;" ::: "memory");
        asm volatile("cp.async.bulk.global.shared::cta.bulk_group [%0], [%1], %2;"
                     :: "l"(cov_o + (size_t)idx0 * 9), "r"(smem_buf),
                        "r"((uint32_t)COV_BYTES) : "memory");
        asm volatile("cp.async.bulk.global.shared::cta.bulk_group [%0], [%1], %2;"
                     :: "l"(har_o + (size_t)idx0 * 12),
                        "r"(smem_buf + (uint32_t)COV_BYTES),
                        "r"((uint32_t)HAR_BYTES) : "memory");
        asm volatile("cp.async.bulk.commit_group;" ::: "memory");
        asm volatile("cp.async.bulk.wait_group.read 0;" ::: "memory");
    }
}

// ============ tail kernel: remainder elements, simple scalar path ============
__global__ void __launch_bounds__(TPB)
mono_gaussian_adapter_tail(
    const float* __restrict__ ext, const float* __restrict__ intr,
    const float* __restrict__ coords, const float* __restrict__ depths,
    const float* __restrict__ opac, const float* __restrict__ rg,
    const unsigned int* __restrict__ hptr, const unsigned int* __restrict__ wptr,
    float* __restrict__ out, int N, int tail_start)
{
    __shared__ CamParams cam;
    const int b   = blockIdx.y;
    const int tid = threadIdx.x;
    const int n   = tail_start + blockIdx.x * TPB + tid;
    const int BN  = (int)gridDim.y * N;
    if (tid == 0) compute_cam(ext, intr, hptr, wptr, b, &cam);
    __syncthreads();
    if (n >= N) return;
    const int idx = b * N + n;

    float2 uv   = ((const float2*)coords)[idx];
    float depth = depths[idx];
    float op    = opac[idx];
    const float* grow = rg + (size_t)idx * 19;
    float sh[12];
#pragma unroll
    for (int i = 0; i < 12; i++) sh[i] = grow[7 + i];

    ElemOut o;
    compute_elem(cam, uv, depth, grow[0], grow[1], grow[2],
                 grow[3], grow[4], grow[5], grow[6], sh, o);

    float* means_o = out;
    float* cov_o   = out + BN * 3;
    float* har_o   = out + BN * 12;
    float* op_o    = out + BN * 24;
    float* sc_o    = out + BN * 25;
    float* rot_o   = out + BN * 28;

    op_o[idx] = op;
    means_o[(size_t)idx * 3 + 0] = o.m0;
    means_o[(size_t)idx * 3 + 1] = o.m1;
    means_o[(size_t)idx * 3 + 2] = o.m2;
    ((float4*)rot_o)[idx] = make_float4(o.qw, o.qx, o.qy, o.qz);
    sc_o[(size_t)idx * 3 + 0] = o.sc0;
    sc_o[(size_t)idx * 3 + 1] = o.sc1;
    sc_o[(size_t)idx * 3 + 2] = o.sc2;
#pragma unroll
    for (int i = 0; i < 9; i++)  cov_o[(size_t)idx * 9 + i] = o.cov[i];
#pragma unroll
    for (int i = 0; i < 12; i++) har_o[(size_t)idx * 12 + i] = o.har[i];
}

extern "C" void kernel_launch(void* const* d_in, const int* in_sizes, int n_in,
                              void* d_out, int out_size)
{
    const float* ext    = (const float*)d_in[0];
    const float* intr   = (const float*)d_in[1];
    const float* coords = (const float*)d_in[2];
    const float* depths = (const float*)d_in[3];
    const float* opac   = (const float*)d_in[4];
    const float* rg     = (const float*)d_in[5];
    const unsigned int* hptr = (const unsigned int*)d_in[6];
    const unsigned int* wptr = (const unsigned int*)d_in[7];
    float* out = (float*)d_out;

    const int B = in_sizes[0] / 16;            // extrinsics: B*1*4*4
    const int N = in_sizes[3] / B;             // depths: B*N

    const int full_tiles = N / TPB;
    const int tail_start = full_tiles * TPB;
    const int rem        = N - tail_start;

    if (full_tiles > 0) {
        dim3 grid(full_tiles, B);
        mono_gaussian_adapter_main<<<grid, TPB>>>(
            ext, intr, coords, depths, opac, rg, hptr, wptr, out, N);
    }
    if (rem > 0) {
        dim3 grid((rem + TPB - 1) / TPB, B);
        mono_gaussian_adapter_tail<<<grid, TPB>>>(
            ext, intr, coords, depths, opac, rg, hptr, wptr, out, N, tail_start);
    }
}